// round 5
// baseline (speedup 1.0000x reference)
#include <cuda_runtime.h>
#include <math.h>

#define WRANKS 4
#define NUM_HEADS 32
#define HEAD_SIZE 128
#define GKV 8              // kv heads
#define QPG 4              // query heads per kv head
#define BLOCK_SIZE 16
#define NUM_BLOCKS 1024
#define MAX_BLOCKS 32
#define MAX_CTX 512
#define NSEQ 32
#define NCHUNK 4
#define CHUNK 128
#define NPER (WRANKS * NCHUNK)                 // 16 partials per (seq, g)
#define NPART (NSEQ * GKV * NPER)              // 4096 partials
#define ATT_SCALE 0.08838834764831845f         // 1/sqrt(128)

// Partial-result scratch — __device__ globals (zero-initialized at load).
__device__ float g_num[NPART][QPG][HEAD_SIZE]; // 8 MB
__device__ float g_m[NPART][QPG];
__device__ float g_e[NPART][QPG];
__device__ int   g_cnt[NSEQ * GKV];            // arrival counters (reset by last CTA)

// P index for (w, s, g, c)
__device__ __forceinline__ int pidx(int w, int s, int g, int c) {
    return ((w * NSEQ + s) * GKV + g) * NCHUNK + c;
}

// ---------------------------------------------------------------------------
// Fused kernel: partial attention + last-block cross-partial LSE merge.
// grid = (NSEQ*GKV, WRANKS, NCHUNK), block = 256
// ---------------------------------------------------------------------------
__global__ __launch_bounds__(256, 4)
void dpa_fused(const float* __restrict__ query,
               const float* __restrict__ key_cache,
               const float* __restrict__ value_cache,
               const int*   __restrict__ block_tables,
               const int*   __restrict__ context_lens,
               float*       __restrict__ out)
{
    __shared__ float smem[2048];             // 8 KB: logits / red buffer / reduce m-e
    __shared__ int   bt_s[MAX_BLOCKS];
    __shared__ float m_s[QPG], e_s[QPG];
    __shared__ int   is_last_s;

    const int sg   = blockIdx.x;             // 0..255
    const int s    = sg >> 3;
    const int g    = sg & 7;
    const int w    = blockIdx.y;
    const int c    = blockIdx.z;
    const int tid  = threadIdx.x;
    const int lane = tid & 31;
    const int warp = tid >> 5;

    const int P = pidx(w, s, g, c);

    const int ctx = context_lens[w * NSEQ + s];
    const int t0  = c * CHUNK;
    const int t1  = min(ctx, t0 + CHUNK);
    const int n   = t1 - t0;

    if (n > 0) {
        if (tid < MAX_BLOCKS)
            bt_s[tid] = block_tables[((size_t)w * NSEQ + s) * MAX_BLOCKS + tid];

        // Q fragments, pre-scaled
        float4 qf[QPG];
        const float* qb = query + (size_t)s * (NUM_HEADS * HEAD_SIZE)
                                + (size_t)g * (QPG * HEAD_SIZE) + lane * 4;
        #pragma unroll
        for (int h = 0; h < QPG; h++) {
            float4 q4 = *(const float4*)(qb + h * HEAD_SIZE);
            q4.x *= ATT_SCALE; q4.y *= ATT_SCALE; q4.z *= ATT_SCALE; q4.w *= ATT_SCALE;
            qf[h] = q4;
        }
        __syncthreads();

        float* logits = smem;  // [QPG][CHUNK]

        const size_t rank_stride = (size_t)NUM_BLOCKS * GKV * BLOCK_SIZE * HEAD_SIZE;
        const size_t page_stride = (size_t)GKV * BLOCK_SIZE * HEAD_SIZE;

        // ---- QK: warp-per-token, 2 tokens in flight --------------------
        const float* kc = key_cache + (size_t)w * rank_stride
                        + (size_t)g * (BLOCK_SIZE * HEAD_SIZE);
        for (int ta = t0 + warp; ta < t1; ta += 16) {
            const int tb = ta + 8;
            const bool hasb = (tb < t1);
            const float* ka = kc + (size_t)bt_s[ta >> 4] * page_stride
                                 + (size_t)(ta & 15) * HEAD_SIZE;
            const float4 k4a = *(const float4*)(ka + lane * 4);
            float4 k4b = make_float4(0.f, 0.f, 0.f, 0.f);
            if (hasb) {
                const float* kb = kc + (size_t)bt_s[tb >> 4] * page_stride
                                     + (size_t)(tb & 15) * HEAD_SIZE;
                k4b = *(const float4*)(kb + lane * 4);
            }
            float pa[QPG], pb[QPG];
            #pragma unroll
            for (int h = 0; h < QPG; h++) {
                float x = k4a.x * qf[h].x;
                x = fmaf(k4a.y, qf[h].y, x);
                x = fmaf(k4a.z, qf[h].z, x);
                x = fmaf(k4a.w, qf[h].w, x);
                pa[h] = x;
                float y = k4b.x * qf[h].x;
                y = fmaf(k4b.y, qf[h].y, y);
                y = fmaf(k4b.z, qf[h].z, y);
                y = fmaf(k4b.w, qf[h].w, y);
                pb[h] = y;
            }
            #pragma unroll
            for (int off = 16; off; off >>= 1) {
                #pragma unroll
                for (int h = 0; h < QPG; h++) {
                    pa[h] += __shfl_xor_sync(0xFFFFFFFFu, pa[h], off);
                    pb[h] += __shfl_xor_sync(0xFFFFFFFFu, pb[h], off);
                }
            }
            if (lane == 0) {
                #pragma unroll
                for (int h = 0; h < QPG; h++) {
                    logits[h * CHUNK + (ta - t0)] = pa[h];
                    if (hasb) logits[h * CHUNK + (tb - t0)] = pb[h];
                }
            }
        }
        __syncthreads();

        // ---- per-head softmax, p in-place ------------------------------
        if (warp < QPG) {
            const int h = warp;
            float mx = -1e30f;
            for (int t = lane; t < n; t += 32)
                mx = fmaxf(mx, logits[h * CHUNK + t]);
            #pragma unroll
            for (int off = 16; off; off >>= 1)
                mx = fmaxf(mx, __shfl_xor_sync(0xFFFFFFFFu, mx, off));
            float sum = 0.0f;
            for (int t = lane; t < n; t += 32) {
                const float p = __expf(logits[h * CHUNK + t] - mx);
                logits[h * CHUNK + t] = p;
                sum += p;
            }
            #pragma unroll
            for (int off = 16; off; off >>= 1)
                sum += __shfl_xor_sync(0xFFFFFFFFu, sum, off);
            if (lane == 0) { m_s[h] = mx; e_s[h] = sum; }
        }
        __syncthreads();

        // ---- PV: 4 independent V loads per thread per page -------------
        const int d2      = tid & 63;
        const int quarter = tid >> 6;
        const float* vc = value_cache + (size_t)w * rank_stride
                        + (size_t)g * (BLOCK_SIZE * HEAD_SIZE) + d2 * 2;
        float2 pv[QPG];
        #pragma unroll
        for (int h = 0; h < QPG; h++) { pv[h].x = 0.0f; pv[h].y = 0.0f; }

        for (int tb = t0; tb < t1; tb += 16) {  // t0 % 16 == 0
            const size_t vbase = (size_t)bt_s[tb >> 4] * page_stride;
            #pragma unroll
            for (int j = 0; j < 4; j++) {
                const int t = tb + quarter + 4 * j;
                if (t < t1) {
                    const float2 v2 = *(const float2*)(vc + vbase
                        + (size_t)(quarter + 4 * j) * HEAD_SIZE);
                    #pragma unroll
                    for (int h = 0; h < QPG; h++) {
                        const float p = logits[h * CHUNK + (t - t0)];
                        pv[h].x = fmaf(p, v2.x, pv[h].x);
                        pv[h].y = fmaf(p, v2.y, pv[h].y);
                    }
                }
            }
        }

        // ---- cross-quarter reduction, write partials -------------------
        __syncthreads();
        float* red = smem;   // [quarter][h][d]
        #pragma unroll
        for (int h = 0; h < QPG; h++) {
            red[quarter * 512 + h * 128 + d2 * 2]     = pv[h].x;
            red[quarter * 512 + h * 128 + d2 * 2 + 1] = pv[h].y;
        }
        __syncthreads();

        const int d  = tid & 127;
        const int h0 = tid >> 7;
        #pragma unroll
        for (int j = 0; j < 2; j++) {
            const int h = h0 + 2 * j;
            g_num[P][h][d] = red[h * 128 + d] + red[512 + h * 128 + d]
                           + red[1024 + h * 128 + d] + red[1536 + h * 128 + d];
        }
        if (tid < QPG) { g_m[P][tid] = m_s[tid]; g_e[P][tid] = e_s[tid]; }
    } else {
        // Empty partial: weight will be exactly 0; skip num writes entirely.
        if (tid < QPG) { g_m[P][tid] = -1e30f; g_e[P][tid] = 0.0f; }
    }

    // ---- last-block arrival + fused reduce ---------------------------------
    __syncthreads();                 // all global writes of this CTA issued
    if (tid == 0) {
        __threadfence();             // release: make them device-visible
        is_last_s = (atomicAdd(&g_cnt[sg], 1) == NPER - 1);
    }
    __syncthreads();
    if (!is_last_s) return;

    __threadfence();                 // acquire side before reading peers' data

    // Load m/e for all 16 partials x 4 heads into smem
    float* sm = smem;                // [NPER][QPG]
    float* se = smem + NPER * QPG;
    if (tid < NPER * QPG) {
        const int p = tid >> 2, h = tid & 3;
        const int Pq = pidx(p >> 2, s, g, p & 3);   // p = w*4 + c
        sm[tid] = g_m[Pq][h];
        se[p * QPG + h] = g_e[Pq][h];
    }
    __syncthreads();

    #pragma unroll
    for (int it = 0; it < 2; it++) {
        const int idx = tid + it * 256;     // 0..511 = (h, d)
        const int h = idx >> 7, d = idx & 127;
        float gmax = -1e30f;
        #pragma unroll
        for (int p = 0; p < NPER; p++)
            gmax = fmaxf(gmax, sm[p * QPG + h]);
        float den = 0.0f, val = 0.0f;
        #pragma unroll
        for (int p = 0; p < NPER; p++) {
            const float wgt = __expf(sm[p * QPG + h] - gmax);
            const int Pq = pidx(p >> 2, s, g, p & 3);
            den = fmaf(se[p * QPG + h], wgt, den);
            val = fmaf(g_num[Pq][h][d], wgt, val);
        }
        out[(size_t)sg * (QPG * HEAD_SIZE) + h * HEAD_SIZE + d] = val / den;
    }

    // Reset counter for the next graph replay
    if (tid == 0) g_cnt[sg] = 0;
}

extern "C" void kernel_launch(void* const* d_in, const int* in_sizes, int n_in,
                              void* d_out, int out_size)
{
    const float* query        = (const float*)d_in[0];
    const float* key_cache    = (const float*)d_in[1];
    const float* value_cache  = (const float*)d_in[2];
    const int*   block_tables = (const int*)d_in[3];
    const int*   context_lens = (const int*)d_in[4];
    float*       out          = (float*)d_out;

    dim3 grid(NSEQ * GKV, WRANKS, NCHUNK);
    dpa_fused<<<grid, 256>>>(query, key_cache, value_cache,
                             block_tables, context_lens, out);
}

// round 6
// speedup vs baseline: 1.0985x; 1.0985x over previous
#include <cuda_runtime.h>
#include <math.h>

#define WRANKS 4
#define NUM_HEADS 32
#define HEAD_SIZE 128
#define GKV 8              // kv heads
#define QPG 4              // query heads per kv head
#define BLOCK_SIZE 16
#define NUM_BLOCKS 1024
#define MAX_BLOCKS 32
#define MAX_CTX 512
#define NSEQ 32
#define NCHUNK 4
#define CHUNK 128
#define NPER (WRANKS * NCHUNK)                 // 16 partials per (seq, g)
#define NPART (NSEQ * GKV * NPER)              // 4096 partials
#define ATT_SCALE 0.08838834764831845f         // 1/sqrt(128)

// Partial-result scratch — __device__ globals (zero-initialized at load).
__device__ float g_num[NPART][QPG][HEAD_SIZE]; // 8 MB
__device__ float g_m[NPART][QPG];
__device__ float g_e[NPART][QPG];
__device__ int   g_cnt[NSEQ * GKV];            // arrival counters (reset by last CTA)

__device__ __forceinline__ int pidx(int w, int s, int g, int c) {
    return ((w * NSEQ + s) * GKV + g) * NCHUNK + c;
}

// Merge two butterfly-reduction streams: lanes where cond!=0 track y's series,
// others track x's. One SHFL per merge instead of one per value per level.
__device__ __forceinline__ float mergestep(float x, float y, int cond, int d) {
    const float keep = cond ? y : x;
    const float send = cond ? x : y;
    return keep + __shfl_xor_sync(0xFFFFFFFFu, send, d);
}

// ---------------------------------------------------------------------------
// Fused kernel: partial attention + last-block cross-partial LSE merge.
// grid = (NSEQ*GKV, WRANKS, NCHUNK), block = 256
// ---------------------------------------------------------------------------
__global__ __launch_bounds__(256, 4)
void dpa_fused(const float* __restrict__ query,
               const float* __restrict__ key_cache,
               const float* __restrict__ value_cache,
               const int*   __restrict__ block_tables,
               const int*   __restrict__ context_lens,
               float*       __restrict__ out)
{
    __shared__ float smem[4096];             // 16 KB: logits (2KB) / red [8][4][128] / reduce m-e
    __shared__ int   bt_s[MAX_BLOCKS];
    __shared__ float m_s[QPG], e_s[QPG];
    __shared__ int   is_last_s;

    const int sg   = blockIdx.x;             // 0..255
    const int s    = sg >> 3;
    const int g    = sg & 7;
    const int w    = blockIdx.y;
    const int c    = blockIdx.z;
    const int tid  = threadIdx.x;
    const int lane = tid & 31;
    const int warp = tid >> 5;

    const int P = pidx(w, s, g, c);

    const int ctx = context_lens[w * NSEQ + s];
    const int t0  = c * CHUNK;
    const int t1  = min(ctx, t0 + CHUNK);
    const int n   = t1 - t0;

    if (n > 0) {
        if (tid < MAX_BLOCKS)
            bt_s[tid] = block_tables[((size_t)w * NSEQ + s) * MAX_BLOCKS + tid];

        // Q fragments, pre-scaled
        float4 qf[QPG];
        const float* qb = query + (size_t)s * (NUM_HEADS * HEAD_SIZE)
                                + (size_t)g * (QPG * HEAD_SIZE) + lane * 4;
        #pragma unroll
        for (int h = 0; h < QPG; h++) {
            float4 q4 = *(const float4*)(qb + h * HEAD_SIZE);
            q4.x *= ATT_SCALE; q4.y *= ATT_SCALE; q4.z *= ATT_SCALE; q4.w *= ATT_SCALE;
            qf[h] = q4;
        }
        __syncthreads();

        float* logits = smem;  // [QPG][CHUNK]

        const size_t rank_stride = (size_t)NUM_BLOCKS * GKV * BLOCK_SIZE * HEAD_SIZE;
        const size_t page_stride = (size_t)GKV * BLOCK_SIZE * HEAD_SIZE;

        // ---- QK: warp-per-token, 2 tokens per iter, merged 9-SHFL reduce ---
        const float* kc = key_cache + (size_t)w * rank_stride
                        + (size_t)g * (BLOCK_SIZE * HEAD_SIZE);
        const int cb0 = lane & 1, cb1 = lane & 2, cb2 = lane & 4;
        #pragma unroll 2
        for (int ta = t0 + warp; ta < t1; ta += 16) {
            const int tb = ta + 8;
            const bool hasb = (tb < t1);
            const float* ka = kc + (size_t)bt_s[ta >> 4] * page_stride
                                 + (size_t)(ta & 15) * HEAD_SIZE;
            const float4 k4a = *(const float4*)(ka + lane * 4);
            float4 k4b = make_float4(0.f, 0.f, 0.f, 0.f);
            if (hasb) {
                const float* kb = kc + (size_t)bt_s[tb >> 4] * page_stride
                                     + (size_t)(tb & 15) * HEAD_SIZE;
                k4b = *(const float4*)(kb + lane * 4);
            }
            float pa[QPG], pb[QPG];
            #pragma unroll
            for (int h = 0; h < QPG; h++) {
                float x = k4a.x * qf[h].x;
                x = fmaf(k4a.y, qf[h].y, x);
                x = fmaf(k4a.z, qf[h].z, x);
                x = fmaf(k4a.w, qf[h].w, x);
                pa[h] = x;
                float y = k4b.x * qf[h].x;
                y = fmaf(k4b.y, qf[h].y, y);
                y = fmaf(k4b.z, qf[h].z, y);
                y = fmaf(k4b.w, qf[h].w, y);
                pb[h] = y;
            }
            // merged reduction: 8 series (head = bits0-1, token = bit2)
            float r01 = mergestep(pa[0], pa[1], cb0, 1);
            float r23 = mergestep(pa[2], pa[3], cb0, 1);
            float s01 = mergestep(pb[0], pb[1], cb0, 1);
            float s23 = mergestep(pb[2], pb[3], cb0, 1);
            float r = mergestep(r01, r23, cb1, 2);
            float sB = mergestep(s01, s23, cb1, 2);
            float t = mergestep(r, sB, cb2, 4);
            t += __shfl_xor_sync(0xFFFFFFFFu, t, 8);
            t += __shfl_xor_sync(0xFFFFFFFFu, t, 16);
            // lane 0-3: head=lane, token a; lane 4-7: head=lane-4, token b
            if (lane < 4) {
                logits[lane * CHUNK + (ta - t0)] = t;
            } else if (lane < 8 && hasb) {
                logits[(lane - 4) * CHUNK + (tb - t0)] = t;
            }
        }
        __syncthreads();

        // ---- per-head softmax, p in-place ------------------------------
        if (warp < QPG) {
            const int h = warp;
            float mx = -1e30f;
            for (int t = lane; t < n; t += 32)
                mx = fmaxf(mx, logits[h * CHUNK + t]);
            #pragma unroll
            for (int off = 16; off; off >>= 1)
                mx = fmaxf(mx, __shfl_xor_sync(0xFFFFFFFFu, mx, off));
            float sum = 0.0f;
            for (int t = lane; t < n; t += 32) {
                const float p = __expf(logits[h * CHUNK + t] - mx);
                logits[h * CHUNK + t] = p;
                sum += p;
            }
            #pragma unroll
            for (int off = 16; off; off >>= 1)
                sum += __shfl_xor_sync(0xFFFFFFFFu, sum, off);
            if (lane == 0) { m_s[h] = mx; e_s[h] = sum; }
        }
        __syncthreads();

        // ---- PV: warp-per-token, float4 per thread ---------------------
        // thread owns float4 #lane of head dim; warp handles tokens
        // t % 8 == warp within each 16-token page (tokens warp, warp+8).
        const float* vc = value_cache + (size_t)w * rank_stride
                        + (size_t)g * (BLOCK_SIZE * HEAD_SIZE) + lane * 4;
        float4 pv[QPG];
        #pragma unroll
        for (int h = 0; h < QPG; h++)
            pv[h] = make_float4(0.f, 0.f, 0.f, 0.f);

        for (int tb = t0; tb < t1; tb += 16) {  // t0 % 16 == 0
            const size_t vbase = (size_t)bt_s[tb >> 4] * page_stride;
            const int taa = tb + warp;
            const int tbb = tb + warp + 8;
            float4 v4a = make_float4(0.f, 0.f, 0.f, 0.f);
            float4 v4b = make_float4(0.f, 0.f, 0.f, 0.f);
            if (taa < t1)
                v4a = *(const float4*)(vc + vbase + (size_t)warp * HEAD_SIZE);
            if (tbb < t1)
                v4b = *(const float4*)(vc + vbase + (size_t)(warp + 8) * HEAD_SIZE);
            if (taa < t1) {
                #pragma unroll
                for (int h = 0; h < QPG; h++) {
                    const float p = logits[h * CHUNK + (taa - t0)];
                    pv[h].x = fmaf(p, v4a.x, pv[h].x);
                    pv[h].y = fmaf(p, v4a.y, pv[h].y);
                    pv[h].z = fmaf(p, v4a.z, pv[h].z);
                    pv[h].w = fmaf(p, v4a.w, pv[h].w);
                }
            }
            if (tbb < t1) {
                #pragma unroll
                for (int h = 0; h < QPG; h++) {
                    const float p = logits[h * CHUNK + (tbb - t0)];
                    pv[h].x = fmaf(p, v4b.x, pv[h].x);
                    pv[h].y = fmaf(p, v4b.y, pv[h].y);
                    pv[h].z = fmaf(p, v4b.z, pv[h].z);
                    pv[h].w = fmaf(p, v4b.w, pv[h].w);
                }
            }
        }

        // ---- cross-warp (8-way) reduction, write partials ---------------
        __syncthreads();
        float4* red = (float4*)smem;   // [8 warps][QPG][32 float4s]
        #pragma unroll
        for (int h = 0; h < QPG; h++)
            red[(warp * QPG + h) * 32 + lane] = pv[h];
        __syncthreads();

        #pragma unroll
        for (int it = 0; it < 2; it++) {
            const int idx = tid + it * 256;     // 0..511 = (h, d)
            const int h = idx >> 7, d = idx & 127;
            float v = 0.0f;
            #pragma unroll
            for (int e = 0; e < 8; e++)
                v += smem[((e * QPG + h) * 32) * 4 + d];
            g_num[P][h][d] = v;
        }
        if (tid < QPG) { g_m[P][tid] = m_s[tid]; g_e[P][tid] = e_s[tid]; }
    } else {
        // Empty partial: weight will be exactly 0; skip num writes entirely.
        if (tid < QPG) { g_m[P][tid] = -1e30f; g_e[P][tid] = 0.0f; }
    }

    // ---- last-block arrival + fused reduce ---------------------------------
    __syncthreads();                 // all global writes of this CTA issued
    if (tid == 0) {
        __threadfence();             // release
        is_last_s = (atomicAdd(&g_cnt[sg], 1) == NPER - 1);
    }
    __syncthreads();
    if (!is_last_s) return;

    __threadfence();                 // acquire

    float* sm = smem;                // [NPER][QPG]
    float* se = smem + NPER * QPG;
    if (tid < NPER * QPG) {
        const int p = tid >> 2, h = tid & 3;
        const int Pq = pidx(p >> 2, s, g, p & 3);   // p = w*4 + c
        sm[tid] = g_m[Pq][h];
        se[p * QPG + h] = g_e[Pq][h];
    }
    __syncthreads();

    #pragma unroll
    for (int it = 0; it < 2; it++) {
        const int idx = tid + it * 256;     // (h, d)
        const int h = idx >> 7, d = idx & 127;
        float gmax = -1e30f;
        #pragma unroll
        for (int p = 0; p < NPER; p++)
            gmax = fmaxf(gmax, sm[p * QPG + h]);
        float den = 0.0f, val = 0.0f;
        #pragma unroll
        for (int p = 0; p < NPER; p++) {
            const float wgt = __expf(sm[p * QPG + h] - gmax);
            const int Pq = pidx(p >> 2, s, g, p & 3);
            den = fmaf(se[p * QPG + h], wgt, den);
            val = fmaf(g_num[Pq][h][d], wgt, val);
        }
        out[(size_t)sg * (QPG * HEAD_SIZE) + h * HEAD_SIZE + d] = val / den;
    }

    if (tid == 0) g_cnt[sg] = 0;
}

extern "C" void kernel_launch(void* const* d_in, const int* in_sizes, int n_in,
                              void* d_out, int out_size)
{
    const float* query        = (const float*)d_in[0];
    const float* key_cache    = (const float*)d_in[1];
    const float* value_cache  = (const float*)d_in[2];
    const int*   block_tables = (const int*)d_in[3];
    const int*   context_lens = (const int*)d_in[4];
    float*       out          = (float*)d_out;

    dim3 grid(NSEQ * GKV, WRANKS, NCHUNK);
    dpa_fused<<<grid, 256>>>(query, key_cache, value_cache,
                             block_tables, context_lens, out);
}